// round 13
// baseline (speedup 1.0000x reference)
#include <cuda_runtime.h>
#include <math.h>

#define NPIX 256
#define NFFT 512
#define KBW  6            // ES kernel width (fine-grid cells)
#define KBHALF 3
#define KBBETA (2.30f * KBW)
#define MUOFF 132         // fft_cols covers mu_signed in [-132, 131]
#define NMU   264

#define NBIN  17          // bins per axis (16-cell tiles over bu in [-132,139])
#define NBIN2 (NBIN * NBIN)
#define CAP   384         // slots per bin (max expected ~260 for 50k uniform)
#define OCAP  4096        // overflow list capacity
#define OVBLOCKS (OCAP / 128)
#define TABN  257         // phi table rows (frac resolution 1/256)
#define TSTR  9           // table row stride (odd -> randomized smem banks)
#define THALO 21          // 16 + KBW - 1

// Scratch (__device__ globals; no allocations). Zero-initialized at load;
// counters are reset by interp_kernel each run (steady-state invariant).
__device__ float d_invd[NPIX];
__device__ __align__(16) float2 d_R[NPIX * NFFT];
__device__ __align__(16) float2 d_F[NFFT * NFFT];   // transposed: F[mu][mv]
__device__ float d_tab[TABN * TSTR];
__device__ int   d_bincnt[NBIN2];
__device__ int   d_binidx[NBIN2 * CAP];
__device__ __align__(8) float2 d_binuv[NBIN2 * CAP];
__device__ int   d_ovcnt;
__device__ int   d_ovdone;
__device__ int   d_ovidx[OCAP];

__device__ __forceinline__ float es_phi(float z) {
    float t = 1.f - z * z * (1.f / (KBHALF * KBHALF));
    return expf(KBBETA * (sqrtf(fmaxf(t, 0.f)) - 1.f));
}

// ---------- Kernel 1 (fused, independent block ranges): ----------
//   blocks [0,256):        deapodization d_invd[x]
//   blocks [256,513):      phi weight table row i = b-256
//   blocks [513,...):      histogram/binning of visibilities
__global__ void __launch_bounds__(128) setup_kernel(const float* __restrict__ uu,
                                                    const float* __restrict__ vv,
                                                    int nvis) {
    const int b = blockIdx.x;
    const int tid = threadIdx.x;

    if (b < 256) {
        // ---- deapodization: psi(xi) = int_{-3}^{3} phi(z) cos(2 pi xi z) dz ----
        __shared__ float red[128];
        const float xi = (float)(b - NPIX / 2) / (float)NFFT;
        const int NQ = 128;
        const float h = (2.f * KBHALF) / NQ;
        float s = 0.f;
        for (int i = tid; i <= NQ; i += 128) {
            float z = -KBHALF + h * i;
            float wgt = (i == 0 || i == NQ) ? 0.5f : 1.f;
            s += wgt * es_phi(z) * cospif(2.f * xi * z);
        }
        red[tid] = s;
        __syncthreads();
        for (int d = 64; d > 0; d >>= 1) {
            if (tid < d) red[tid] += red[tid + d];
            __syncthreads();
        }
        if (tid == 0) d_invd[b] = 1.f / (red[0] * h);
    } else if (b < 256 + TABN) {
        // ---- phi table: tab[i][t] = phi(i/256 + 2 - t), t = 0..5 ----
        int i = b - 256;
        if (tid < KBW) {
            float z = (float)i * (1.f / 256.f) + 2.f - (float)tid;
            d_tab[i * TSTR + tid] = es_phi(z);
        }
    } else {
        // ---- histogram: assign each vis to a (bu,bv) tile bin ----
        int j = (b - (256 + TABN)) * 128 + tid;
        if (j >= nvis) return;
        const float ARCSEC_F = (float)(M_PI / 180.0 / 3600.0);
        const float cell_rad = 0.005f * ARCSEC_F;
        float gu = (float)NFFT * (uu[j] * 1e3f) * cell_rad;   // fine-grid coord
        float gv = (float)NFFT * (vv[j] * 1e3f) * cell_rad;
        int bu = (int)floorf(gu), bv = (int)floorf(gv);
        bool stored = false;
        if (bu >= -132 && bv >= -132) {
            int bx = (bu + 132) >> 4, by = (bv + 132) >> 4;
            if (bx < NBIN && by < NBIN) {
                int bin = by * NBIN + bx;
                int slot = atomicAdd(&d_bincnt[bin], 1);
                if (slot < CAP) {
                    d_binidx[bin * CAP + slot] = j;
                    d_binuv[bin * CAP + slot] = make_float2(gu, gv);
                    stored = true;
                }
            }
        }
        if (!stored) {
            int os = atomicAdd(&d_ovcnt, 1);
            if (os < OCAP) d_ovidx[os] = j;
        }
    }
}

// ---------- Stockham radix-2 512-pt FFT, twiddles from smem table ----------
__device__ __forceinline__ void fft512(float2* bufA, float2* bufB,
                                       const float2* tw, int tid) {
    float2 *src = bufA, *dst = bufB;
#pragma unroll
    for (int s = 0; s < 9; ++s) {
        const int L = 1 << s;
        __syncthreads();
        int kk = tid & (L - 1);
        float2 w = tw[kk << (8 - s)];
        float2 a = src[tid], b = src[tid + 256];
        float tbr = b.x * w.x - b.y * w.y;
        float tbi = b.x * w.y + b.y * w.x;
        dst[2 * tid - kk]     = make_float2(a.x + tbr, a.y + tbi);
        dst[2 * tid - kk + L] = make_float2(a.x - tbr, a.y - tbi);
        float2* tmp = src; src = dst; dst = tmp;
    }
    __syncthreads();
}

// ---------- Kernel 2: fused softplus + Hann conv + deapodize + row FFT ----------
__global__ void __launch_bounds__(256) fft_rows_kernel(const float* __restrict__ base) {
    __shared__ float2 bufA[NFFT], bufB[NFFT];
    __shared__ float2 tw[256];
    __shared__ float sp[3][NPIX];
    const int y = blockIdx.x;
    const int tid = threadIdx.x;

    float twr, twi; sincospif(-(float)tid / 256.f, &twi, &twr);
    tw[tid] = make_float2(twr, twi);

#pragma unroll
    for (int d = 0; d < 3; ++d) {
        int yy = y - 1 + d;
        float v = 0.f;
        if (yy >= 0 && yy < NPIX) {
            float bb = base[yy * NPIX + tid];
            v = fmaxf(bb, 0.f) + log1pf(expf(-fabsf(bb)));
        }
        sp[d][tid] = v;
    }
    __syncthreads();

    float acc = 0.f;
    {
        const float hy[3] = {0.25f, 0.5f, 0.25f};
#pragma unroll
        for (int d = 0; d < 3; ++d) {
            float l = (tid > 0)        ? sp[d][tid - 1] : 0.f;
            float m = sp[d][tid];
            float r = (tid < NPIX - 1) ? sp[d][tid + 1] : 0.f;
            acc += hy[d] * (0.25f * l + 0.5f * m + 0.25f * r);
        }
    }
    float val = acc * d_invd[y] * d_invd[tid];

    int j = (tid >= 128) ? (tid - 128) : (tid + 384);
    bufA[128 + tid] = make_float2(0.f, 0.f);
    __syncthreads();
    bufA[j] = make_float2(val, 0.f);

    fft512(bufA, bufB, tw, tid);
    d_R[y * NFFT + tid]       = bufB[tid];
    d_R[y * NFFT + tid + 256] = bufB[tid + 256];
}

// ---------- Kernel 3: column FFTs, only needed mu; transposed store ----------
__global__ void __launch_bounds__(256) fft_cols_kernel() {
    __shared__ float2 bufA[NFFT], bufB[NFFT];
    __shared__ float2 tw[256];
    const int tid = threadIdx.x;
    const int mu = (blockIdx.x - MUOFF) & (NFFT - 1);

    float twr, twi; sincospif(-(float)tid / 256.f, &twi, &twr);
    tw[tid] = make_float2(twr, twi);

    int j = (tid >= 128) ? (tid - 128) : (tid + 384);
    bufA[128 + tid] = make_float2(0.f, 0.f);
    __syncthreads();
    bufA[j] = d_R[tid * NFFT + mu];

    fft512(bufA, bufB, tw, tid);
    d_F[mu * NFFT + tid]       = bufB[tid];
    d_F[mu * NFFT + tid + 256] = bufB[tid + 256];
}

// ---------- Kernel 4: tile-binned interpolation ----------
// blocks [0,289): one bin each — halo tile + weight table in SMEM, thread/vis.
// blocks [289,321): overflow fallback — direct global gather (normally empty).
__global__ void __launch_bounds__(128) interp_kernel(const float* __restrict__ uu,
                                                     const float* __restrict__ vv,
                                                     float* __restrict__ out,
                                                     int nvis, int mode) {
    const int tid = threadIdx.x;
    const float ARCSEC_F = (float)(M_PI / 180.0 / 3600.0);
    const float cell_rad = 0.005f * ARCSEC_F;
    const float c2 = cell_rad * cell_rad;

    if (blockIdx.x < NBIN2) {
        __shared__ float2 stile[THALO * THALO];
        __shared__ float  stab[TABN * TSTR];
        const int b = blockIdx.x;
        const int bx = b % NBIN, by = b / NBIN;
        const int bu_low = 16 * bx - 132, bv_low = 16 * by - 132;

        for (int i = tid; i < TABN * TSTR; i += 128) stab[i] = d_tab[i];
        for (int i = tid; i < THALO * THALO; i += 128) {
            int r = i / THALO, cc = i - THALO * r;
            int mu = (bu_low - 2 + r) & (NFFT - 1);
            int mv = (bv_low - 2 + cc) & (NFFT - 1);
            stile[i] = d_F[mu * NFFT + mv];
        }
        __syncthreads();

        int cnt = d_bincnt[b];
        if (cnt > CAP) cnt = CAP;
        for (int s0 = 0; s0 < cnt; s0 += 128) {
            int s = s0 + tid;
            if (s < cnt) {
                float2 g = d_binuv[b * CAP + s];
                int k = d_binidx[b * CAP + s];
                int bu = (int)floorf(g.x), bv = (int)floorf(g.y);
                float xu = (g.x - (float)bu) * 256.f;
                float xv = (g.y - (float)bv) * 256.f;
                int iu = (int)xu, iv = (int)xv;
                float au = xu - (float)iu, av = xv - (float)iv;
                float wu[KBW], wv[KBW];
#pragma unroll
                for (int t = 0; t < KBW; ++t) {
                    float a0 = stab[iu * TSTR + t], a1 = stab[(iu + 1) * TSTR + t];
                    wu[t] = a0 + au * (a1 - a0);
                    float b0 = stab[iv * TSTR + t], b1 = stab[(iv + 1) * TSTR + t];
                    wv[t] = b0 + av * (b1 - b0);
                }
                int du = bu - bu_low, dv = bv - bv_low;   // in [0,15]
                float vr = 0.f, vi = 0.f;
#pragma unroll
                for (int tu = 0; tu < KBW; ++tu) {
                    const float2* row = &stile[(du + tu) * THALO + dv];
                    float rr = 0.f, ri = 0.f;
#pragma unroll
                    for (int tv = 0; tv < KBW; ++tv) {
                        float2 f = row[tv];
                        rr += wv[tv] * f.x;
                        ri += wv[tv] * f.y;
                    }
                    vr += wu[tu] * rr;
                    vi += wu[tu] * ri;
                }
                float orr = vr * c2, oii = vi * c2;
                if (mode == 0) out[k] = orr;
                else { out[2 * k + 0] = orr; out[2 * k + 1] = oii; }
            }
        }
        __syncthreads();
        if (tid == 0) d_bincnt[b] = 0;   // reset for next replay
    } else {
        // ---- overflow fallback: direct gather from global F ----
        int oc = d_ovcnt;
        if (oc > OCAP) oc = OCAP;
        int j = (blockIdx.x - NBIN2) * 128 + tid;
        if (j < oc) {
            int k = d_ovidx[j];
            float gu = (float)NFFT * (uu[k] * 1e3f) * cell_rad;
            float gv = (float)NFFT * (vv[k] * 1e3f) * cell_rad;
            int bu = (int)floorf(gu), bv = (int)floorf(gv);
            float xu = (gu - (float)bu) * 256.f;
            float xv = (gv - (float)bv) * 256.f;
            int iu = (int)xu, iv = (int)xv;
            float au = xu - (float)iu, av = xv - (float)iv;
            float wu[KBW], wv[KBW];
#pragma unroll
            for (int t = 0; t < KBW; ++t) {
                float a0 = d_tab[iu * TSTR + t], a1 = d_tab[(iu + 1) * TSTR + t];
                wu[t] = a0 + au * (a1 - a0);
                float b0 = d_tab[iv * TSTR + t], b1 = d_tab[(iv + 1) * TSTR + t];
                wv[t] = b0 + av * (b1 - b0);
            }
            float vr = 0.f, vi = 0.f;
#pragma unroll
            for (int tu = 0; tu < KBW; ++tu) {
                int mu = (bu - 2 + tu) & (NFFT - 1);
                float rr = 0.f, ri = 0.f;
#pragma unroll
                for (int tv = 0; tv < KBW; ++tv) {
                    int mv = (bv - 2 + tv) & (NFFT - 1);
                    float2 f = d_F[mu * NFFT + mv];
                    rr += wv[tv] * f.x;
                    ri += wv[tv] * f.y;
                }
                vr += wu[tu] * rr;
                vi += wu[tu] * ri;
            }
            float orr = vr * c2, oii = vi * c2;
            if (mode == 0) out[k] = orr;
            else { out[2 * k + 0] = orr; out[2 * k + 1] = oii; }
        }
        __syncthreads();
        if (tid == 0) {
            // last overflow block to finish resets the counters
            if (atomicAdd(&d_ovdone, 1) == OVBLOCKS - 1) {
                d_ovcnt = 0;
                d_ovdone = 0;
            }
        }
    }
}

extern "C" void kernel_launch(void* const* d_in, const int* in_sizes, int n_in,
                              void* d_out, int out_size) {
    // Input mapping by size (proven R4-R12): image is the 65536-element input;
    // the remaining two, in order, are uu then vv.
    int img_i = -1;
    for (int i = 0; i < n_in; ++i)
        if (in_sizes[i] == NPIX * NPIX) { img_i = i; break; }
    if (img_i < 0) img_i = 0;
    int uv_idx[2]; int c = 0;
    for (int i = 0; i < n_in && c < 2; ++i)
        if (i != img_i) uv_idx[c++] = i;

    const float* base = (const float*)d_in[img_i];
    const float* uu   = (const float*)d_in[uv_idx[0]];
    const float* vv   = (const float*)d_in[uv_idx[1]];
    float* out = (float*)d_out;
    const int nvis = in_sizes[uv_idx[0]];

    // Output-mode logic (proven R4-R12).
    int mode = (out_size >= 2 * nvis) ? 1 : 0;

    int nhist = (nvis + 127) / 128;
    setup_kernel<<<256 + TABN + nhist, 128>>>(uu, vv, nvis);
    fft_rows_kernel<<<NPIX, 256>>>(base);
    fft_cols_kernel<<<NMU, 256>>>();
    interp_kernel<<<NBIN2 + OVBLOCKS, 128>>>(uu, vv, out, nvis, mode);
}

// round 14
// speedup vs baseline: 1.4451x; 1.4451x over previous
#include <cuda_runtime.h>
#include <math.h>

#define NPIX 256
#define NFFT 512
#define KBW  6            // ES kernel width (fine-grid cells)
#define KBHALF 3
#define KBBETA (2.30f * KBW)
#define MUOFF 132         // fft_cols covers mu_signed in [-132, 131]
#define NMU   264

// Scratch (__device__ globals; no allocations)
__device__ float d_invd[NPIX];                           // 1/psi((x-128)/512)
__device__ __align__(16) float2 d_R[NPIX * NFFT];        // row FFTs: R[y][mu]
__device__ __align__(16) float2 d_F[NFFT * NFFT];        // spectrum, TRANSPOSED: F[mu][mv]

// ---------- ES spreading kernel ----------
// accurate version (setup/deapodization only)
__device__ __forceinline__ float es_phi(float z) {
    float t = 1.f - z * z * (1.f / (KBHALF * KBHALF));
    return expf(KBBETA * (sqrtf(fmaxf(t, 0.f)) - 1.f));
}
// fast-intrinsic version (interp hot path): __expf/__fsqrt_rn, err ~1e-6
__device__ __forceinline__ float es_phi_fast(float z) {
    float t = 1.f - z * z * (1.f / (KBHALF * KBHALF));
    return __expf(KBBETA * (__fsqrt_rn(fmaxf(t, 0.f)) - 1.f));
}

// ---------- Kernel A: deapodization table (1 block per x) ----------
__global__ void __launch_bounds__(128) dpd_kernel() {
    __shared__ float red[128];
    const int x = blockIdx.x;
    const int tid = threadIdx.x;
    const float xi = (float)(x - NPIX / 2) / (float)NFFT;
    const int NQ = 128;
    const float h = (2.f * KBHALF) / NQ;
    float s = 0.f;
    for (int i = tid; i <= NQ; i += 128) {
        float z = -KBHALF + h * i;
        float c = cospif(2.f * xi * z);
        float wgt = (i == 0 || i == NQ) ? 0.5f : 1.f;
        s += wgt * es_phi(z) * c;
    }
    red[tid] = s;
    __syncthreads();
    for (int d = 64; d > 0; d >>= 1) {
        if (tid < d) red[tid] += red[tid + d];
        __syncthreads();
    }
    if (tid == 0) d_invd[x] = 1.f / (red[0] * h);
}

// ---------- Stockham radix-2 512-pt FFT, twiddles from smem table ----------
// tw[m] = exp(-i*pi*m/256), m=0..255. Result ends in bufB.
__device__ __forceinline__ void fft512(float2* bufA, float2* bufB,
                                       const float2* tw, int tid) {
    float2 *src = bufA, *dst = bufB;
#pragma unroll
    for (int s = 0; s < 9; ++s) {
        const int L = 1 << s;
        __syncthreads();
        int kk = tid & (L - 1);
        float2 w = tw[kk << (8 - s)];
        float2 a = src[tid], b = src[tid + 256];
        float tbr = b.x * w.x - b.y * w.y;
        float tbi = b.x * w.y + b.y * w.x;
        dst[2 * tid - kk]     = make_float2(a.x + tbr, a.y + tbi);
        dst[2 * tid - kk + L] = make_float2(a.x - tbr, a.y - tbi);
        float2* tmp = src; src = dst; dst = tmp;
    }
    __syncthreads();
}

// ---------- Kernel B: fused softplus + Hann conv + deapodize + row FFT ----------
__global__ void __launch_bounds__(256) fft_rows_kernel(const float* __restrict__ base) {
    __shared__ float2 bufA[NFFT], bufB[NFFT];
    __shared__ float2 tw[256];
    __shared__ float sp[3][NPIX];
    const int y = blockIdx.x;
    const int tid = threadIdx.x;

    float twr, twi; sincospif(-(float)tid / 256.f, &twi, &twr);
    tw[tid] = make_float2(twr, twi);

#pragma unroll
    for (int d = 0; d < 3; ++d) {
        int yy = y - 1 + d;
        float v = 0.f;
        if (yy >= 0 && yy < NPIX) {
            float b = base[yy * NPIX + tid];
            v = fmaxf(b, 0.f) + log1pf(expf(-fabsf(b)));
        }
        sp[d][tid] = v;
    }
    __syncthreads();

    float acc = 0.f;
    {
        const float hy[3] = {0.25f, 0.5f, 0.25f};
#pragma unroll
        for (int d = 0; d < 3; ++d) {
            float l = (tid > 0)        ? sp[d][tid - 1] : 0.f;
            float m = sp[d][tid];
            float r = (tid < NPIX - 1) ? sp[d][tid + 1] : 0.f;
            acc += hy[d] * (0.25f * l + 0.5f * m + 0.25f * r);
        }
    }
    float val = acc * d_invd[y] * d_invd[tid];

    int j = (tid >= 128) ? (tid - 128) : (tid + 384);
    bufA[128 + tid] = make_float2(0.f, 0.f);
    __syncthreads();
    bufA[j] = make_float2(val, 0.f);

    fft512(bufA, bufB, tw, tid);
    d_R[y * NFFT + tid]       = bufB[tid];
    d_R[y * NFFT + tid + 256] = bufB[tid + 256];
}

// ---------- Kernel C: column FFTs, only needed mu; TRANSPOSED coalesced store ----------
__global__ void __launch_bounds__(256) fft_cols_kernel() {
    __shared__ float2 bufA[NFFT], bufB[NFFT];
    __shared__ float2 tw[256];
    const int tid = threadIdx.x;
    const int mu = (blockIdx.x - MUOFF) & (NFFT - 1);

    float twr, twi; sincospif(-(float)tid / 256.f, &twi, &twr);
    tw[tid] = make_float2(twr, twi);

    int j = (tid >= 128) ? (tid - 128) : (tid + 384);
    bufA[128 + tid] = make_float2(0.f, 0.f);
    __syncthreads();
    bufA[j] = d_R[tid * NFFT + mu];

    fft512(bufA, bufB, tw, tid);
    d_F[mu * NFFT + tid]       = bufB[tid];
    d_F[mu * NFFT + tid + 256] = bufB[tid + 256];
}

// ---------- Kernel D: one-warp-per-visibility 6x6 interpolation ----------
// Tap i: tu=i/6, tv=i%6. Lane i handles tap i (i<32); lanes 0-3 also taps 32-35.
// Taps of one vis live in 6 rows x 48B -> ~12 L1 line-touches/vis (best shape).
// es_phi_fast: __expf/__fsqrt_rn intrinsics (the R12 version was libm-routine-bound).
__global__ void __launch_bounds__(256) interp_kernel(const float* __restrict__ uu,
                              const float* __restrict__ vv,
                              float* __restrict__ out, int nvis, int mode) {
    const int lane = threadIdx.x & 31;
    const int k = blockIdx.x * 8 + (threadIdx.x >> 5);   // 8 warps/CTA, 1 vis/warp
    if (k >= nvis) return;

    const float ARCSEC_F = (float)(M_PI / 180.0 / 3600.0);
    const float cell_rad = 0.005f * ARCSEC_F;
    const float fu = (uu[k] * 1e3f) * cell_rad;          // |fu| <= 0.25
    const float fv = (vv[k] * 1e3f) * cell_rad;
    const float gu = (float)NFFT * fu;
    const float gv = (float)NFFT * fv;
    const int bu = (int)floorf(gu);
    const int bv = (int)floorf(gv);

    float vr = 0.f, vi = 0.f;
#pragma unroll
    for (int pass = 0; pass < 2; ++pass) {
        int i = lane + pass * 32;
        if (i < KBW * KBW) {
            int tu = i / KBW, tv = i - tu * KBW;
            float wu = es_phi_fast(gu - (float)(bu - 2 + tu));
            float wv = es_phi_fast(gv - (float)(bv - 2 + tv));
            int mu = (bu - 2 + tu) & (NFFT - 1);
            int mv = (bv - 2 + tv) & (NFFT - 1);
            float2 f = __ldg(&d_F[mu * NFFT + mv]);
            float w = wu * wv;
            vr += w * f.x;
            vi += w * f.y;
        }
    }

    // full-warp reduction
#pragma unroll
    for (int off = 16; off > 0; off >>= 1) {
        vr += __shfl_down_sync(0xffffffffu, vr, off);
        vi += __shfl_down_sync(0xffffffffu, vi, off);
    }

    if (lane == 0) {
        float c2 = cell_rad * cell_rad;
        float orr = vr * c2;
        float oii = vi * c2;
        if (mode == 0) {
            out[k] = orr;
        } else {
            out[2 * k + 0] = orr;
            out[2 * k + 1] = oii;
        }
    }
}

extern "C" void kernel_launch(void* const* d_in, const int* in_sizes, int n_in,
                              void* d_out, int out_size) {
    // Input mapping by size (proven R4-R13): image is the 65536-element input;
    // the remaining two, in order, are uu then vv.
    int img_i = -1;
    for (int i = 0; i < n_in; ++i)
        if (in_sizes[i] == NPIX * NPIX) { img_i = i; break; }
    if (img_i < 0) img_i = 0;
    int uv_idx[2]; int c = 0;
    for (int i = 0; i < n_in && c < 2; ++i)
        if (i != img_i) uv_idx[c++] = i;

    const float* base = (const float*)d_in[img_i];
    const float* uu   = (const float*)d_in[uv_idx[0]];
    const float* vv   = (const float*)d_in[uv_idx[1]];
    float* out = (float*)d_out;
    const int nvis = in_sizes[uv_idx[0]];

    // Output-mode logic (proven R4-R13).
    int mode = (out_size >= 2 * nvis) ? 1 : 0;

    dpd_kernel<<<NPIX, 128>>>();
    fft_rows_kernel<<<NPIX, 256>>>(base);
    fft_cols_kernel<<<NMU, 256>>>();
    interp_kernel<<<(nvis + 7) / 8, 256>>>(uu, vv, out, nvis, mode);
}

// round 15
// speedup vs baseline: 1.5671x; 1.0845x over previous
#include <cuda_runtime.h>
#include <math.h>

#define NPIX 256
#define NFFT 512
#define KBW  5            // ES kernel width (fine-grid cells)
#define KBHALF 2.5f
#define KBBETA (2.30f * KBW)   // 11.5
#define MUOFF 132         // fft_cols covers mu_signed in [-132, 131]
#define NMU   264

// Scratch (__device__ globals; no allocations)
__device__ float d_invd[NPIX];                           // 1/psi((x-128)/512)
__device__ __align__(16) float2 d_R[NPIX * NFFT];        // row FFTs: R[y][mu]
__device__ __align__(16) float2 d_F[NFFT * NFFT];        // spectrum, TRANSPOSED: F[mu][mv]

// ---------- ES spreading kernel ----------
__device__ __forceinline__ float es_phi(float z) {
    float t = 1.f - z * z * (1.f / (KBHALF * KBHALF));
    return expf(KBBETA * (sqrtf(fmaxf(t, 0.f)) - 1.f));
}
__device__ __forceinline__ float es_phi_fast(float z) {
    float t = 1.f - z * z * (1.f / (KBHALF * KBHALF));
    return __expf(KBBETA * (__fsqrt_rn(fmaxf(t, 0.f)) - 1.f));
}

// ---------- Kernel A: deapodization table (1 block per x) ----------
__global__ void __launch_bounds__(128) dpd_kernel() {
    __shared__ float red[128];
    const int x = blockIdx.x;
    const int tid = threadIdx.x;
    const float xi = (float)(x - NPIX / 2) / (float)NFFT;
    const int NQ = 128;
    const float h = (2.f * KBHALF) / NQ;
    float s = 0.f;
    for (int i = tid; i <= NQ; i += 128) {
        float z = -KBHALF + h * i;
        float c = cospif(2.f * xi * z);
        float wgt = (i == 0 || i == NQ) ? 0.5f : 1.f;
        s += wgt * es_phi(z) * c;
    }
    red[tid] = s;
    __syncthreads();
    for (int d = 64; d > 0; d >>= 1) {
        if (tid < d) red[tid] += red[tid + d];
        __syncthreads();
    }
    if (tid == 0) d_invd[x] = 1.f / (red[0] * h);
}

// ---------- Stockham radix-2 512-pt FFT, twiddles from smem table ----------
__device__ __forceinline__ void fft512(float2* bufA, float2* bufB,
                                       const float2* tw, int tid) {
    float2 *src = bufA, *dst = bufB;
#pragma unroll
    for (int s = 0; s < 9; ++s) {
        const int L = 1 << s;
        __syncthreads();
        int kk = tid & (L - 1);
        float2 w = tw[kk << (8 - s)];
        float2 a = src[tid], b = src[tid + 256];
        float tbr = b.x * w.x - b.y * w.y;
        float tbi = b.x * w.y + b.y * w.x;
        dst[2 * tid - kk]     = make_float2(a.x + tbr, a.y + tbi);
        dst[2 * tid - kk + L] = make_float2(a.x - tbr, a.y - tbi);
        float2* tmp = src; src = dst; dst = tmp;
    }
    __syncthreads();
}

// ---------- Kernel B: fused softplus + Hann conv + deapodize + row FFT ----------
__global__ void __launch_bounds__(256) fft_rows_kernel(const float* __restrict__ base) {
    __shared__ float2 bufA[NFFT], bufB[NFFT];
    __shared__ float2 tw[256];
    __shared__ float sp[3][NPIX];
    const int y = blockIdx.x;
    const int tid = threadIdx.x;

    float twr, twi; sincospif(-(float)tid / 256.f, &twi, &twr);
    tw[tid] = make_float2(twr, twi);

#pragma unroll
    for (int d = 0; d < 3; ++d) {
        int yy = y - 1 + d;
        float v = 0.f;
        if (yy >= 0 && yy < NPIX) {
            float b = base[yy * NPIX + tid];
            v = fmaxf(b, 0.f) + log1pf(expf(-fabsf(b)));
        }
        sp[d][tid] = v;
    }
    __syncthreads();

    float acc = 0.f;
    {
        const float hy[3] = {0.25f, 0.5f, 0.25f};
#pragma unroll
        for (int d = 0; d < 3; ++d) {
            float l = (tid > 0)        ? sp[d][tid - 1] : 0.f;
            float m = sp[d][tid];
            float r = (tid < NPIX - 1) ? sp[d][tid + 1] : 0.f;
            acc += hy[d] * (0.25f * l + 0.5f * m + 0.25f * r);
        }
    }
    float val = acc * d_invd[y] * d_invd[tid];

    int j = (tid >= 128) ? (tid - 128) : (tid + 384);
    bufA[128 + tid] = make_float2(0.f, 0.f);
    __syncthreads();
    bufA[j] = make_float2(val, 0.f);

    fft512(bufA, bufB, tw, tid);
    d_R[y * NFFT + tid]       = bufB[tid];
    d_R[y * NFFT + tid + 256] = bufB[tid + 256];
}

// ---------- Kernel C: column FFTs, only needed mu; TRANSPOSED coalesced store ----------
__global__ void __launch_bounds__(256) fft_cols_kernel() {
    __shared__ float2 bufA[NFFT], bufB[NFFT];
    __shared__ float2 tw[256];
    const int tid = threadIdx.x;
    const int mu = (blockIdx.x - MUOFF) & (NFFT - 1);

    float twr, twi; sincospif(-(float)tid / 256.f, &twi, &twr);
    tw[tid] = make_float2(twr, twi);

    int j = (tid >= 128) ? (tid - 128) : (tid + 384);
    bufA[128 + tid] = make_float2(0.f, 0.f);
    __syncthreads();
    bufA[j] = d_R[tid * NFFT + mu];

    fft512(bufA, bufB, tw, tid);
    d_F[mu * NFFT + tid]       = bufB[tid];
    d_F[mu * NFFT + tid + 256] = bufB[tid + 256];
}

// ---------- Kernel D: one-warp-per-visibility 5x5 interpolation ----------
// Round-to-nearest centering: taps m = bu-2+t, z = g-m in [-2.5, 2.5].
// Lanes 0-4 compute wu/wv once; all lanes fetch via shfl. Lane i<25: tap
// (tu,tv) = (i/5, i%5) with i/5 = (i*52)>>8 (exact for i<25). Single pass.
__global__ void __launch_bounds__(256) interp_kernel(const float* __restrict__ uu,
                              const float* __restrict__ vv,
                              float* __restrict__ out, int nvis, int mode) {
    const int lane = threadIdx.x & 31;
    const int k = blockIdx.x * 8 + (threadIdx.x >> 5);   // 8 warps/CTA, 1 vis/warp
    if (k >= nvis) return;

    const float ARCSEC_F = (float)(M_PI / 180.0 / 3600.0);
    const float cell_rad = 0.005f * ARCSEC_F;
    const float fu = (uu[k] * 1e3f) * cell_rad;          // |fu| <= 0.25
    const float fv = (vv[k] * 1e3f) * cell_rad;
    const float gu = (float)NFFT * fu;
    const float gv = (float)NFFT * fv;
    const int bu = (int)floorf(gu + 0.5f);               // round to nearest
    const int bv = (int)floorf(gv + 0.5f);
    const float du = gu - (float)bu;                     // in [-0.5, 0.5]
    const float dv = gv - (float)bv;

    // per-lane weight seeds (meaningful for lane < 5)
    float wu_own = es_phi_fast(du + 2.f - (float)lane);
    float wv_own = es_phi_fast(dv + 2.f - (float)lane);

    const int tu = (lane * 52) >> 8;          // lane/5 for lane<25
    const int tv = lane - 5 * tu;
    float wu = __shfl_sync(0xffffffffu, wu_own, tu);
    float wv = __shfl_sync(0xffffffffu, wv_own, tv);

    int mu = (bu - 2 + tu) & (NFFT - 1);
    int mv = (bv - 2 + tv) & (NFFT - 1);
    float2 f = __ldg(&d_F[mu * NFFT + mv]);
    float w = (lane < 25) ? wu * wv : 0.f;
    float vr = w * f.x;
    float vi = w * f.y;

    // full-warp reduction
#pragma unroll
    for (int off = 16; off > 0; off >>= 1) {
        vr += __shfl_down_sync(0xffffffffu, vr, off);
        vi += __shfl_down_sync(0xffffffffu, vi, off);
    }

    if (lane == 0) {
        float c2 = cell_rad * cell_rad;
        float orr = vr * c2;
        float oii = vi * c2;
        if (mode == 0) {
            out[k] = orr;
        } else {
            out[2 * k + 0] = orr;
            out[2 * k + 1] = oii;
        }
    }
}

extern "C" void kernel_launch(void* const* d_in, const int* in_sizes, int n_in,
                              void* d_out, int out_size) {
    // Input mapping by size (proven R4-R14): image is the 65536-element input;
    // the remaining two, in order, are uu then vv.
    int img_i = -1;
    for (int i = 0; i < n_in; ++i)
        if (in_sizes[i] == NPIX * NPIX) { img_i = i; break; }
    if (img_i < 0) img_i = 0;
    int uv_idx[2]; int c = 0;
    for (int i = 0; i < n_in && c < 2; ++i)
        if (i != img_i) uv_idx[c++] = i;

    const float* base = (const float*)d_in[img_i];
    const float* uu   = (const float*)d_in[uv_idx[0]];
    const float* vv   = (const float*)d_in[uv_idx[1]];
    float* out = (float*)d_out;
    const int nvis = in_sizes[uv_idx[0]];

    // Output-mode logic (proven R4-R14).
    int mode = (out_size >= 2 * nvis) ? 1 : 0;

    dpd_kernel<<<NPIX, 128>>>();
    fft_rows_kernel<<<NPIX, 256>>>(base);
    fft_cols_kernel<<<NMU, 256>>>();
    interp_kernel<<<(nvis + 7) / 8, 256>>>(uu, vv, out, nvis, mode);
}

// round 16
// speedup vs baseline: 1.8554x; 1.1839x over previous
#include <cuda_runtime.h>
#include <math.h>

#define NPIX 256
#define NFFT 512
#define KBW  5            // ES kernel width (fine-grid cells)
#define KBHALF 2.5f
#define KBBETA (2.30f * KBW)   // 11.5
#define MUOFF 132         // cols cover mu_signed in [-132, 131]
#define NMU   264
#define ITPB 352          // interp: 143 CTAs x 352 = 50336 >= 50000, single wave

// Scratch (__device__ globals; no allocations)
__device__ float d_invd[NPIX];                           // 1/psi((x-128)/512)
__device__ __align__(16) float2 d_R[NPIX * NFFT];        // row FFTs: R[y][mu]
__device__ __align__(16) float2 d_F[NFFT * NFFT];        // spectrum, TRANSPOSED: F[mu][mv]

// ---------- ES spreading kernel ----------
__device__ __forceinline__ float es_phi(float z) {
    float t = 1.f - z * z * (1.f / (KBHALF * KBHALF));
    return expf(KBBETA * (sqrtf(fmaxf(t, 0.f)) - 1.f));
}
__device__ __forceinline__ float es_phi_fast(float z) {
    float t = 1.f - z * z * (1.f / (KBHALF * KBHALF));
    return __expf(KBBETA * (__fsqrt_rn(fmaxf(t, 0.f)) - 1.f));
}

// ---------- Kernel A: deapodization table (1 block per x) ----------
__global__ void __launch_bounds__(128) dpd_kernel() {
    __shared__ float red[128];
    const int x = blockIdx.x;
    const int tid = threadIdx.x;
    const float xi = (float)(x - NPIX / 2) / (float)NFFT;
    const int NQ = 128;
    const float h = (2.f * KBHALF) / NQ;
    float s = 0.f;
    for (int i = tid; i <= NQ; i += 128) {
        float z = -KBHALF + h * i;
        float c = cospif(2.f * xi * z);
        float wgt = (i == 0 || i == NQ) ? 0.5f : 1.f;
        s += wgt * es_phi(z) * c;
    }
    red[tid] = s;
    __syncthreads();
    for (int d = 64; d > 0; d >>= 1) {
        if (tid < d) red[tid] += red[tid + d];
        __syncthreads();
    }
    if (tid == 0) d_invd[x] = 1.f / (red[0] * h);
}

// ---------- Dual Stockham radix-2 512-pt FFT ----------
// 512 threads = 2 independent FFTs (halves run in lockstep; shared syncs legal).
// tw[m] = exp(-i*pi*m/256). Result ends in buf1[h].
__device__ __forceinline__ void fft512_dual(float2 (*buf0)[NFFT], float2 (*buf1)[NFFT],
                                            const float2* tw, int h, int t) {
    float2 *src = buf0[h], *dst = buf1[h];
#pragma unroll
    for (int s = 0; s < 9; ++s) {
        const int L = 1 << s;
        __syncthreads();
        int kk = t & (L - 1);
        float2 w = tw[kk << (8 - s)];
        float2 a = src[t], b = src[t + 256];
        float tbr = b.x * w.x - b.y * w.y;
        float tbi = b.x * w.y + b.y * w.x;
        dst[2 * t - kk]     = make_float2(a.x + tbr, a.y + tbi);
        dst[2 * t - kk + L] = make_float2(a.x - tbr, a.y - tbi);
        float2* tmp = src; src = dst; dst = tmp;
    }
    __syncthreads();
}

// ---------- Kernel B: fused softplus + Hann conv + deapodize + row FFT ----------
// CTA b handles rows y0=2b, y0+1 (128 CTAs = single wave).
__global__ void __launch_bounds__(512) fft_rows_kernel(const float* __restrict__ base) {
    __shared__ float2 buf0[2][NFFT], buf1[2][NFFT];
    __shared__ float2 tw[256];
    __shared__ float sp[4][NPIX];
    const int tid = threadIdx.x;
    const int h = tid >> 8;          // which row of the pair
    const int t = tid & 255;
    const int y0 = blockIdx.x * 2;

    if (tid < 256) {
        float twr, twi; sincospif(-(float)tid / 256.f, &twi, &twr);
        tw[tid] = make_float2(twr, twi);
    }

    // softplus of the 4 needed base rows: y0-1 .. y0+2
    for (int i = tid; i < 4 * NPIX; i += 512) {
        int d = i >> 8, x = i & 255;
        int yy = y0 - 1 + d;
        float v = 0.f;
        if (yy >= 0 && yy < NPIX) {
            float b = base[yy * NPIX + x];
            v = fmaxf(b, 0.f) + log1pf(expf(-fabsf(b)));
        }
        sp[d][x] = v;
    }
    __syncthreads();

    // 3x3 Hann conv at (y0+h, x=t): rows sp[h..h+2]
    float acc = 0.f;
    {
        const float hy[3] = {0.25f, 0.5f, 0.25f};
#pragma unroll
        for (int d = 0; d < 3; ++d) {
            float l = (t > 0)        ? sp[h + d][t - 1] : 0.f;
            float m = sp[h + d][t];
            float r = (t < NPIX - 1) ? sp[h + d][t + 1] : 0.f;
            acc += hy[d] * (0.25f * l + 0.5f * m + 0.25f * r);
        }
    }
    float val = acc * d_invd[y0 + h] * d_invd[t];

    int j = (t >= 128) ? (t - 128) : (t + 384);
    buf0[h][128 + t] = make_float2(0.f, 0.f);
    __syncthreads();
    buf0[h][j] = make_float2(val, 0.f);

    fft512_dual(buf0, buf1, tw, h, t);
    d_R[(y0 + h) * NFFT + t]       = buf1[h][t];
    d_R[(y0 + h) * NFFT + t + 256] = buf1[h][t + 256];
}

// ---------- Kernel C: column FFTs, 2 per CTA (132 CTAs = single wave) ----------
__global__ void __launch_bounds__(512) fft_cols_kernel() {
    __shared__ float2 buf0[2][NFFT], buf1[2][NFFT];
    __shared__ float2 tw[256];
    const int tid = threadIdx.x;
    const int h = tid >> 8;
    const int t = tid & 255;
    const int mu = (blockIdx.x * 2 + h - MUOFF) & (NFFT - 1);

    if (tid < 256) {
        float twr, twi; sincospif(-(float)tid / 256.f, &twi, &twr);
        tw[tid] = make_float2(twr, twi);
    }

    int j = (t >= 128) ? (t - 128) : (t + 384);
    buf0[h][128 + t] = make_float2(0.f, 0.f);
    __syncthreads();
    buf0[h][j] = d_R[t * NFFT + mu];

    fft512_dual(buf0, buf1, tw, h, t);
    // transposed store: F[mu][mv], mv contiguous -> coalesced
    d_F[mu * NFFT + t]       = buf1[h][t];
    d_F[mu * NFFT + t + 256] = buf1[h][t + 256];
}

// ---------- Kernel D: thread-per-visibility 5x5 interpolation ----------
// Round-to-nearest centering. 25 loads batched first (MLP~25), then separable
// FMA pass. No shuffles, no reduction — minimal per-vis overhead.
__global__ void __launch_bounds__(ITPB) interp_kernel(const float* __restrict__ uu,
                              const float* __restrict__ vv,
                              float* __restrict__ out, int nvis, int mode) {
    const int k = blockIdx.x * ITPB + threadIdx.x;
    if (k >= nvis) return;

    const float ARCSEC_F = (float)(M_PI / 180.0 / 3600.0);
    const float cell_rad = 0.005f * ARCSEC_F;
    const float gu = (float)NFFT * (uu[k] * 1e3f) * cell_rad;   // |gu| <= 128
    const float gv = (float)NFFT * (vv[k] * 1e3f) * cell_rad;
    const int bu = (int)floorf(gu + 0.5f);
    const int bv = (int)floorf(gv + 0.5f);
    const float du = gu - (float)bu;                            // in [-0.5, 0.5]
    const float dv = gv - (float)bv;

    float wu[KBW], wv[KBW];
#pragma unroll
    for (int tap = 0; tap < KBW; ++tap) {
        wu[tap] = es_phi_fast(du + 2.f - (float)tap);
        wv[tap] = es_phi_fast(dv + 2.f - (float)tap);
    }

    // batched loads (independent; compiler hoists into one MLP group)
    float2 f[KBW * KBW];
#pragma unroll
    for (int tu = 0; tu < KBW; ++tu) {
        const int mu = (bu - 2 + tu) & (NFFT - 1);
        const float2* Fcol = &d_F[mu * NFFT];
#pragma unroll
        for (int tv = 0; tv < KBW; ++tv) {
            int mv = (bv - 2 + tv) & (NFFT - 1);
            f[tu * KBW + tv] = __ldg(&Fcol[mv]);
        }
    }

    // separable accumulate
    float vr = 0.f, vi = 0.f;
#pragma unroll
    for (int tu = 0; tu < KBW; ++tu) {
        float rr = 0.f, ri = 0.f;
#pragma unroll
        for (int tv = 0; tv < KBW; ++tv) {
            rr += wv[tv] * f[tu * KBW + tv].x;
            ri += wv[tv] * f[tu * KBW + tv].y;
        }
        vr += wu[tu] * rr;
        vi += wu[tu] * ri;
    }

    const float c2 = cell_rad * cell_rad;
    float orr = vr * c2;
    float oii = vi * c2;
    if (mode == 0) {
        out[k] = orr;
    } else {
        out[2 * k + 0] = orr;
        out[2 * k + 1] = oii;
    }
}

extern "C" void kernel_launch(void* const* d_in, const int* in_sizes, int n_in,
                              void* d_out, int out_size) {
    // Input mapping by size (proven R4-R15): image is the 65536-element input;
    // the remaining two, in order, are uu then vv.
    int img_i = -1;
    for (int i = 0; i < n_in; ++i)
        if (in_sizes[i] == NPIX * NPIX) { img_i = i; break; }
    if (img_i < 0) img_i = 0;
    int uv_idx[2]; int c = 0;
    for (int i = 0; i < n_in && c < 2; ++i)
        if (i != img_i) uv_idx[c++] = i;

    const float* base = (const float*)d_in[img_i];
    const float* uu   = (const float*)d_in[uv_idx[0]];
    const float* vv   = (const float*)d_in[uv_idx[1]];
    float* out = (float*)d_out;
    const int nvis = in_sizes[uv_idx[0]];

    // Output-mode logic (proven R4-R15).
    int mode = (out_size >= 2 * nvis) ? 1 : 0;

    dpd_kernel<<<NPIX, 128>>>();
    fft_rows_kernel<<<NPIX / 2, 512>>>(base);
    fft_cols_kernel<<<NMU / 2, 512>>>();
    interp_kernel<<<(nvis + ITPB - 1) / ITPB, ITPB>>>(uu, vv, out, nvis, mode);
}

// round 17
// speedup vs baseline: 1.9753x; 1.0646x over previous
#include <cuda_runtime.h>
#include <math.h>

#define NPIX 256
#define NFFT 512
#define KBW  5            // ES kernel width (fine-grid cells)
#define KBHALF 2.5f
#define KBBETA (2.30f * KBW)   // 11.5
#define MUOFF 132         // cols cover mu_signed in [-132, 131]
#define NMU   264
#define ITPB 704          // interp: 2 thr/vis, 143 CTAs x 704 = single wave

// Scratch (__device__ globals; no allocations)
__device__ __align__(16) float2 d_R[NPIX * NFFT];        // row FFTs: R[y][mu]
__device__ __align__(16) float2 d_F[NFFT * NFFT];        // spectrum, TRANSPOSED: F[mu][mv]

// ---------- ES spreading kernel (fast intrinsics; err ~1e-6) ----------
__device__ __forceinline__ float es_phi_fast(float z) {
    float t = 1.f - z * z * (1.f / (KBHALF * KBHALF));
    return __expf(KBBETA * (__fsqrt_rn(fmaxf(t, 0.f)) - 1.f));
}

// ---------- Dual Stockham radix-2 512-pt FFT ----------
// 512 threads = 2 independent FFTs (halves run in lockstep; shared syncs legal).
// tw[m] = exp(-i*pi*m/256). Result ends in buf1[h].
__device__ __forceinline__ void fft512_dual(float2 (*buf0)[NFFT], float2 (*buf1)[NFFT],
                                            const float2* tw, int h, int t) {
    float2 *src = buf0[h], *dst = buf1[h];
#pragma unroll
    for (int s = 0; s < 9; ++s) {
        const int L = 1 << s;
        __syncthreads();
        int kk = t & (L - 1);
        float2 w = tw[kk << (8 - s)];
        float2 a = src[t], b = src[t + 256];
        float tbr = b.x * w.x - b.y * w.y;
        float tbi = b.x * w.y + b.y * w.x;
        dst[2 * t - kk]     = make_float2(a.x + tbr, a.y + tbi);
        dst[2 * t - kk + L] = make_float2(a.x - tbr, a.y - tbi);
        float2* tmp = src; src = dst; dst = tmp;
    }
    __syncthreads();
}

// ---------- Kernel B: fused deapodize + softplus + Hann conv + row FFT ----------
// CTA b handles rows y0=2b, y0+1 (128 CTAs = single wave).
// Deapodization inline: psi(xi) = int phi(z)cos(2 pi xi z)dz via theta-substitution
// z = 2.5 sin(theta): integrand exp(beta(cos t - 1)) cos(5 pi xi sin t) 2.5 cos t,
// 20-pt midpoint (integrand ~e^-beta at endpoints -> spectral accuracy).
__global__ void __launch_bounds__(512) fft_rows_kernel(const float* __restrict__ base) {
    __shared__ float2 buf0[2][NFFT], buf1[2][NFFT];
    __shared__ float2 tw[256];
    __shared__ float sp[4][NPIX];
    __shared__ float invd_s[NPIX];
    const int tid = threadIdx.x;
    const int h = tid >> 8;          // which row of the pair
    const int t = tid & 255;
    const int y0 = blockIdx.x * 2;

    if (tid < 256) {
        float twr, twi; sincospif(-(float)tid / 256.f, &twi, &twr);
        tw[tid] = make_float2(twr, twi);
        // inline deapodization for xi = (tid-128)/512
        float xi = (float)(tid - NPIX / 2) * (1.f / (float)NFFT);
        float sum = 0.f;
#pragma unroll
        for (int i = 0; i < 20; ++i) {
            float s_i, c_i;
            sincospif((float)(i) * 0.05f + 0.025f - 0.5f, &s_i, &c_i); // theta_i/pi
            float e = __expf(KBBETA * (c_i - 1.f));
            sum += e * c_i * cospif(2.f * KBHALF * xi * s_i);
        }
        invd_s[tid] = 1.f / (sum * KBHALF * (float)M_PI / 20.f);
    }

    // softplus of the 4 needed base rows: y0-1 .. y0+2
    for (int i = tid; i < 4 * NPIX; i += 512) {
        int d = i >> 8, x = i & 255;
        int yy = y0 - 1 + d;
        float v = 0.f;
        if (yy >= 0 && yy < NPIX) {
            float b = base[yy * NPIX + x];
            v = fmaxf(b, 0.f) + log1pf(expf(-fabsf(b)));
        }
        sp[d][x] = v;
    }
    __syncthreads();

    // 3x3 Hann conv at (y0+h, x=t): rows sp[h..h+2]
    float acc = 0.f;
    {
        const float hy[3] = {0.25f, 0.5f, 0.25f};
#pragma unroll
        for (int d = 0; d < 3; ++d) {
            float l = (t > 0)        ? sp[h + d][t - 1] : 0.f;
            float m = sp[h + d][t];
            float r = (t < NPIX - 1) ? sp[h + d][t + 1] : 0.f;
            acc += hy[d] * (0.25f * l + 0.5f * m + 0.25f * r);
        }
    }
    float val = acc * invd_s[y0 + h] * invd_s[t];

    int j = (t >= 128) ? (t - 128) : (t + 384);
    buf0[h][128 + t] = make_float2(0.f, 0.f);
    __syncthreads();
    buf0[h][j] = make_float2(val, 0.f);

    fft512_dual(buf0, buf1, tw, h, t);
    d_R[(y0 + h) * NFFT + t]       = buf1[h][t];
    d_R[(y0 + h) * NFFT + t + 256] = buf1[h][t + 256];
}

// ---------- Kernel C: column FFTs, 2 per CTA (132 CTAs = single wave) ----------
__global__ void __launch_bounds__(512) fft_cols_kernel() {
    __shared__ float2 buf0[2][NFFT], buf1[2][NFFT];
    __shared__ float2 tw[256];
    const int tid = threadIdx.x;
    const int h = tid >> 8;
    const int t = tid & 255;
    const int mu = (blockIdx.x * 2 + h - MUOFF) & (NFFT - 1);

    if (tid < 256) {
        float twr, twi; sincospif(-(float)tid / 256.f, &twi, &twr);
        tw[tid] = make_float2(twr, twi);
    }

    int j = (t >= 128) ? (t - 128) : (t + 384);
    buf0[h][128 + t] = make_float2(0.f, 0.f);
    __syncthreads();
    buf0[h][j] = d_R[t * NFFT + mu];

    fft512_dual(buf0, buf1, tw, h, t);
    // transposed store: F[mu][mv], mv contiguous -> coalesced
    d_F[mu * NFFT + t]       = buf1[h][t];
    d_F[mu * NFFT + t + 256] = buf1[h][t + 256];
}

// ---------- Kernel D: 2-threads-per-visibility 5x5 interpolation ----------
// Lane pair (2m, 2m+1) shares vis k: p=0 handles tap rows tu={0,2,4},
// p=1 handles tu={1,3}. One shfl_xor combine. 100K threads = 22 warps/SM.
__global__ void __launch_bounds__(ITPB) interp_kernel(const float* __restrict__ uu,
                              const float* __restrict__ vv,
                              float* __restrict__ out, int nvis, int mode) {
    const int tid = threadIdx.x;
    const int p = tid & 1;
    const int k = blockIdx.x * (ITPB / 2) + (tid >> 1);
    const bool valid = (k < nvis);

    const float ARCSEC_F = (float)(M_PI / 180.0 / 3600.0);
    const float cell_rad = 0.005f * ARCSEC_F;

    float vr = 0.f, vi = 0.f;
    if (valid) {
        const float gu = (float)NFFT * (uu[k] * 1e3f) * cell_rad;   // |gu| <= 128
        const float gv = (float)NFFT * (vv[k] * 1e3f) * cell_rad;
        const int bu = (int)floorf(gu + 0.5f);
        const int bv = (int)floorf(gv + 0.5f);
        const float du = gu - (float)bu;                            // in [-0.5, 0.5]
        const float dv = gv - (float)bv;

        float wv[KBW];
#pragma unroll
        for (int tap = 0; tap < KBW; ++tap)
            wv[tap] = es_phi_fast(dv + 2.f - (float)tap);

        const int ntu = p ? 2 : 3;
#pragma unroll
        for (int s = 0; s < 3; ++s) {
            if (s < ntu) {
                const int tu = 2 * s + p;                 // p=0: 0,2,4; p=1: 1,3
                const float wu = es_phi_fast(du + 2.f - (float)tu);
                const int mu = (bu - 2 + tu) & (NFFT - 1);
                const float2* Fcol = &d_F[mu * NFFT];
                float rr = 0.f, ri = 0.f;
#pragma unroll
                for (int tv = 0; tv < KBW; ++tv) {
                    int mv = (bv - 2 + tv) & (NFFT - 1);
                    float2 f = __ldg(&Fcol[mv]);
                    rr += wv[tv] * f.x;
                    ri += wv[tv] * f.y;
                }
                vr += wu * rr;
                vi += wu * ri;
            }
        }
    }

    // combine the lane pair (no divergent return above: all threads arrive)
    vr += __shfl_xor_sync(0xffffffffu, vr, 1);
    vi += __shfl_xor_sync(0xffffffffu, vi, 1);

    if (valid && p == 0) {
        const float c2 = cell_rad * cell_rad;
        float orr = vr * c2;
        float oii = vi * c2;
        if (mode == 0) {
            out[k] = orr;
        } else {
            out[2 * k + 0] = orr;
            out[2 * k + 1] = oii;
        }
    }
}

extern "C" void kernel_launch(void* const* d_in, const int* in_sizes, int n_in,
                              void* d_out, int out_size) {
    // Input mapping by size (proven R4-R16): image is the 65536-element input;
    // the remaining two, in order, are uu then vv.
    int img_i = -1;
    for (int i = 0; i < n_in; ++i)
        if (in_sizes[i] == NPIX * NPIX) { img_i = i; break; }
    if (img_i < 0) img_i = 0;
    int uv_idx[2]; int c = 0;
    for (int i = 0; i < n_in && c < 2; ++i)
        if (i != img_i) uv_idx[c++] = i;

    const float* base = (const float*)d_in[img_i];
    const float* uu   = (const float*)d_in[uv_idx[0]];
    const float* vv   = (const float*)d_in[uv_idx[1]];
    float* out = (float*)d_out;
    const int nvis = in_sizes[uv_idx[0]];

    // Output-mode logic (proven R4-R16).
    int mode = (out_size >= 2 * nvis) ? 1 : 0;

    fft_rows_kernel<<<NPIX / 2, 512>>>(base);
    fft_cols_kernel<<<NMU / 2, 512>>>();
    interp_kernel<<<(2 * nvis + ITPB - 1) / ITPB, ITPB>>>(uu, vv, out, nvis, mode);
}